// round 8
// baseline (speedup 1.0000x reference)
#include <cuda_runtime.h>
#include <math.h>

typedef unsigned long long ull;

#define CB 32
#define CT 40
#define CP 12
#define CE 2048
#define CH 1024
#define CM (CB*CT*CP)     /* 15360 rows of (b,t,p) */
#define CBP (CB*CP)       /* 384 GRU state rows */

/* ---------------- scratch (device globals; no allocation allowed) -------- */
__device__ float g_x  [CM * CH];        /* embed output, 63 MB  */
__device__ float g_gx [CM * 3 * CH];    /* input gates, 189 MB  */
__device__ float g_hid[CM * CH];        /* all hiddens, 63 MB   */
__device__ float g_h0 [CBP * CH];
__device__ float g_h1 [CBP * CH];

/* ---------------- packed fp32x2 FMA (Blackwell FFMA2) -------------------- */
__device__ __forceinline__ void ffma2(ull& d, ull a, ull b) {
    asm("fma.rn.f32x2 %0, %1, %2, %0;" : "+l"(d) : "l"(a), "l"(b));
}
__device__ __forceinline__ float2 upk(ull v) {
    return *reinterpret_cast<float2*>(&v);
}

/* ================= big GEMM: C[m,n] = act(A[m,:]·W[n,:] + b[n]) ==========
 * Tile 128x128, BK=8, 256 threads, DOUBLE-BUFFERED smem (1 sync/chunk).
 * Accumulators paired along M; A natural (broadcast LDS.128), W duplicated
 * (w,w) so two adjacent columns come from one conflict-free LDS.128.
 * Inner loop per kk: 2 a-LDS.128 + 4 b-LDS.128 + 32 FFMA2.               */
#define BM 128
#define BN 128
#define BKc 8

#define G_STORE(P) do { \
    As[P][lk+0][lr] = pa.x; As[P][lk+1][lr] = pa.y; \
    As[P][lk+2][lr] = pa.z; As[P][lk+3][lr] = pa.w; \
    *(float2*)&Bs[P][lk+0][2*lr] = make_float2(pb.x, pb.x); \
    *(float2*)&Bs[P][lk+1][2*lr] = make_float2(pb.y, pb.y); \
    *(float2*)&Bs[P][lk+2][2*lr] = make_float2(pb.z, pb.z); \
    *(float2*)&Bs[P][lk+3][2*lr] = make_float2(pb.w, pb.w); } while (0)

#define G_COMPUTE(P) do { \
    _Pragma("unroll") \
    for (int kk = 0; kk < BKc; ++kk) { \
        ulonglong2 a0 = *(const ulonglong2*)&As[P][kk][ty*8]; \
        ulonglong2 a1 = *(const ulonglong2*)&As[P][kk][ty*8 + 4]; \
        ull am[4] = {a0.x, a0.y, a1.x, a1.y}; \
        ull bd[8]; \
        _Pragma("unroll") \
        for (int q = 0; q < 4; q++) { \
            ulonglong2 bq = *(const ulonglong2*)&Bs[P][kk][q*64 + 4*tx]; \
            bd[2*q] = bq.x; bd[2*q+1] = bq.y; \
        } \
        _Pragma("unroll") \
        for (int mp = 0; mp < 4; mp++) \
            _Pragma("unroll") \
            for (int n = 0; n < 8; n++) ffma2(acc[mp][n], am[mp], bd[n]); \
    } } while (0)

__global__ __launch_bounds__(256) void gemm_f32x2(
    const float* __restrict__ A, const float* __restrict__ W,
    const float* __restrict__ bias, float* __restrict__ C,
    int N, int K, int act)
{
    __shared__ __align__(16) float As[2][BKc][BM + 4];
    __shared__ __align__(16) float Bs[2][BKc][2*BN + 8];

    const int tid = threadIdx.x;
    const int tx  = tid & 15;          /* col group            */
    const int ty  = tid >> 4;          /* rows ty*8..ty*8+7    */
    const int lr  = tid >> 1;          /* loader row 0..127    */
    const int lk  = (tid & 1) << 2;    /* loader k offset      */

    const float* Ag = A + (size_t)(blockIdx.y * BM + lr) * K + lk;
    const float* Wg = W + (size_t)(blockIdx.x * BN + lr) * K + lk;

    ull acc[4][8];
#pragma unroll
    for (int i = 0; i < 4; i++)
#pragma unroll
        for (int j = 0; j < 8; j++) acc[i][j] = 0ULL;

    float4 pa = *(const float4*)Ag;
    float4 pb = *(const float4*)Wg;
    G_STORE(0);
    __syncthreads();

    const int nch = K / BKc;           /* even: 256 or 128 */
    for (int c = 0; c < nch; c += 2) {
        /* phase A: compute buf0, prefetch+store chunk c+1 into buf1 */
        pa = *(const float4*)(Ag + (size_t)(c+1)*BKc);
        pb = *(const float4*)(Wg + (size_t)(c+1)*BKc);
        G_COMPUTE(0);
        G_STORE(1);
        __syncthreads();
        /* phase B: compute buf1, prefetch+store chunk c+2 into buf0 */
        if (c + 2 < nch) {
            pa = *(const float4*)(Ag + (size_t)(c+2)*BKc);
            pb = *(const float4*)(Wg + (size_t)(c+2)*BKc);
        }
        G_COMPUTE(1);
        if (c + 2 < nch) G_STORE(0);
        __syncthreads();
    }

    /* epilogue: acc[mp][2q+jj] = (row 2mp, row 2mp+1) at col 32q+2tx+jj */
    const int colb = blockIdx.x * BN;
    float2 bb[4];
#pragma unroll
    for (int q = 0; q < 4; q++)
        bb[q] = *(const float2*)&bias[colb + 32*q + 2*tx];
#pragma unroll
    for (int mp = 0; mp < 4; mp++) {
#pragma unroll
        for (int half = 0; half < 2; half++) {
            int row = blockIdx.y * BM + ty*8 + 2*mp + half;
            float* Cr = C + (size_t)row * N + colb;
#pragma unroll
            for (int q = 0; q < 4; q++) {
                float2 e = upk(acc[mp][2*q]);
                float2 o = upk(acc[mp][2*q+1]);
                float2 v;
                v.x = (half ? e.y : e.x) + bb[q].x;
                v.y = (half ? o.y : o.x) + bb[q].y;
                if (act) { v.x = tanhf(v.x); v.y = tanhf(v.y); }
                *(float2*)&Cr[32*q + 2*tx] = v;
            }
        }
    }
}

/* ================= fused GRU step ========================================
 * Tile 64 m x 16 j x 3 gates, 128 threads, grid (64, 6) = 384 blocks so the
 * whole chip is covered with multiple co-resident blocks per SM.
 * Thread (tx=tid&7, ty=tid>>3): rows 4ty..4ty+3 (2 m-pairs), cols
 * j0+2tx, j0+2tx+1. Double-buffered smem; inner loop per kk:
 * 1 a-LDS.128 + 3 b-LDS.128 + 12 FFMA2, all conflict-free.               */
#define GBM 64
#define GBJ 16

#define R_STORE(P) do { \
    As[P][lk+0][lr] = pa.x; As[P][lk+1][lr] = pa.y; \
    As[P][lk+2][lr] = pa.z; As[P][lk+3][lr] = pa.w; \
    if (tid < 96) { \
        *(float2*)&Bs[P][lk+0][2*lr] = make_float2(pb.x, pb.x); \
        *(float2*)&Bs[P][lk+1][2*lr] = make_float2(pb.y, pb.y); \
        *(float2*)&Bs[P][lk+2][2*lr] = make_float2(pb.z, pb.z); \
        *(float2*)&Bs[P][lk+3][2*lr] = make_float2(pb.w, pb.w); \
    } } while (0)

#define R_COMPUTE(P) do { \
    _Pragma("unroll") \
    for (int kk = 0; kk < BKc; ++kk) { \
        ulonglong2 aq = *(const ulonglong2*)&As[P][kk][4*ty]; \
        ull am[2] = {aq.x, aq.y}; \
        ull bd[3][2]; \
        _Pragma("unroll") \
        for (int g = 0; g < 3; g++) { \
            ulonglong2 bq = *(const ulonglong2*)&Bs[P][kk][g*32 + 4*tx]; \
            bd[g][0] = bq.x; bd[g][1] = bq.y; \
        } \
        _Pragma("unroll") \
        for (int mp = 0; mp < 2; mp++) \
            _Pragma("unroll") \
            for (int g = 0; g < 3; g++) { \
                ffma2(acc[mp][g][0], am[mp], bd[g][0]); \
                ffma2(acc[mp][g][1], am[mp], bd[g][1]); \
            } \
    } } while (0)

__global__ __launch_bounds__(128) void gru_step(
    const float* __restrict__ h_in, float* __restrict__ h_out,
    const float* __restrict__ gx, const float* __restrict__ W_hh,
    const float* __restrict__ b_hh, float* __restrict__ hid, int t)
{
    __shared__ __align__(16) float As[2][BKc][GBM + 4];      /* h, natural   */
    __shared__ __align__(16) float Bs[2][BKc][2*48 + 8];     /* W, dup (w,w) */

    const int tid = threadIdx.x;
    const int tx  = tid & 7;           /* cols j0+2tx, j0+2tx+1 */
    const int ty  = tid >> 3;          /* rows 4ty..4ty+3       */
    const int m0  = blockIdx.y * GBM;
    const int j0  = blockIdx.x * GBJ;

    const int lr = tid >> 1, lk = (tid & 1) << 2;
    const float* Ag = h_in + (size_t)(m0 + lr) * CH + lk;       /* 128 thr */
    const float* Wg;
    {   /* tid<96: B row lr in 0..47 -> gate lr>>4, col j0+(lr&15) */
        int g = lr >> 4;
        int j = j0 + (lr & 15);
        Wg = W_hh + (size_t)(g * CH + j) * CH + lk;
    }

    ull acc[2][3][2];
#pragma unroll
    for (int i = 0; i < 2; i++)
#pragma unroll
        for (int g = 0; g < 3; g++) { acc[i][g][0] = 0ULL; acc[i][g][1] = 0ULL; }

    float4 pa = *(const float4*)Ag;
    float4 pb;
    if (tid < 96) pb = *(const float4*)Wg;
    R_STORE(0);
    __syncthreads();

    const int nch = CH / BKc;   /* 128, even */
    for (int c = 0; c < nch; c += 2) {
        pa = *(const float4*)(Ag + (size_t)(c+1)*BKc);
        if (tid < 96) pb = *(const float4*)(Wg + (size_t)(c+1)*BKc);
        R_COMPUTE(0);
        R_STORE(1);
        __syncthreads();
        if (c + 2 < nch) {
            pa = *(const float4*)(Ag + (size_t)(c+2)*BKc);
            if (tid < 96) pb = *(const float4*)(Wg + (size_t)(c+2)*BKc);
        }
        R_COMPUTE(1);
        if (c + 2 < nch) R_STORE(0);
        __syncthreads();
    }

    /* epilogue: GRU elementwise update (4 m-rows x 2 j-cols per thread) */
    const int jb = j0 + 2*tx;
    float2 bhr = *(const float2*)&b_hh[jb];
    float2 bhz = *(const float2*)&b_hh[CH + jb];
    float2 bhn = *(const float2*)&b_hh[2*CH + jb];
#pragma unroll
    for (int mp = 0; mp < 2; mp++) {
        float2 r0 = upk(acc[mp][0][0]), r1 = upk(acc[mp][0][1]);
        float2 z0 = upk(acc[mp][1][0]), z1 = upk(acc[mp][1][1]);
        float2 n0 = upk(acc[mp][2][0]), n1 = upk(acc[mp][2][1]);
#pragma unroll
        for (int half = 0; half < 2; half++) {
            int m = m0 + 4*ty + 2*mp + half;
            int b = m / CP, p = m - b * CP;
            size_t grow = (size_t)(b * CT + t) * CP + p;
            const float* gxr = gx + grow * (3*CH);
            float2 xr = *(const float2*)&gxr[jb];
            float2 xz = *(const float2*)&gxr[CH + jb];
            float2 xn = *(const float2*)&gxr[2*CH + jb];
            float2 hold = *(const float2*)&h_in[(size_t)m * CH + jb];
            float ghr0 = (half ? r0.y : r0.x) + bhr.x;
            float ghr1 = (half ? r1.y : r1.x) + bhr.y;
            float ghz0 = (half ? z0.y : z0.x) + bhz.x;
            float ghz1 = (half ? z1.y : z1.x) + bhz.y;
            float ghn0 = (half ? n0.y : n0.x) + bhn.x;
            float ghn1 = (half ? n1.y : n1.x) + bhn.y;
            float r_0 = 1.f / (1.f + expf(-(xr.x + ghr0)));
            float r_1 = 1.f / (1.f + expf(-(xr.y + ghr1)));
            float z_0 = 1.f / (1.f + expf(-(xz.x + ghz0)));
            float z_1 = 1.f / (1.f + expf(-(xz.y + ghz1)));
            float n_0 = tanhf(xn.x + r_0 * ghn0);
            float n_1 = tanhf(xn.y + r_1 * ghn1);
            float2 hn;
            hn.x = (1.f - z_0) * n_0 + z_0 * hold.x;
            hn.y = (1.f - z_1) * n_1 + z_1 * hold.y;
            *(float2*)&h_out[(size_t)m * CH + jb] = hn;
            *(float2*)&hid[grow * CH + jb]        = hn;
        }
    }
}

/* ---------------- heads -------------------------------------------------- */
__global__ __launch_bounds__(256) void action_head(
    const float* __restrict__ hid, const float* __restrict__ W,
    const float* __restrict__ bias, float* __restrict__ out)
{
    __shared__ float Ws[9 * CH];
    for (int i = threadIdx.x; i < 9 * CH; i += 256) Ws[i] = W[i];
    __syncthreads();
    const int warp = threadIdx.x >> 5, lane = threadIdx.x & 31;
    const int m = blockIdx.x * 8 + warp;
    const float* hr = hid + (size_t)m * CH;
    float p[9];
#pragma unroll
    for (int a = 0; a < 9; a++) p[a] = 0.f;
    for (int kk = 0; kk < CH/32; kk++) {
        int k = lane + 32*kk;
        float v = hr[k];
#pragma unroll
        for (int a = 0; a < 9; a++) p[a] += v * Ws[a*CH + k];
    }
#pragma unroll
    for (int a = 0; a < 9; a++) {
        float s = p[a];
#pragma unroll
        for (int o = 16; o > 0; o >>= 1) s += __shfl_down_sync(0xffffffffu, s, o);
        if (lane == 0) out[(size_t)m * 9 + a] = s + bias[a];
    }
}

__global__ __launch_bounds__(256) void activity_head(
    const float* __restrict__ hid, const float* __restrict__ W,
    const float* __restrict__ bias, float* __restrict__ out)
{
    __shared__ float Ws[8 * CH];
    for (int i = threadIdx.x; i < 8 * CH; i += 256) Ws[i] = W[i];
    __syncthreads();
    const int warp = threadIdx.x >> 5, lane = threadIdx.x & 31;
    const int bt = blockIdx.x * 8 + warp;                 /* (b*T+t) */
    const float* base = hid + (size_t)bt * CP * CH;
    float p[8];
#pragma unroll
    for (int a = 0; a < 8; a++) p[a] = 0.f;
    for (int kk = 0; kk < CH/32; kk++) {
        int k = lane + 32*kk;
        float v = base[k];
#pragma unroll
        for (int pp = 1; pp < CP; pp++) v = fmaxf(v, base[(size_t)pp*CH + k]);
#pragma unroll
        for (int a = 0; a < 8; a++) p[a] += v * Ws[a*CH + k];
    }
#pragma unroll
    for (int a = 0; a < 8; a++) {
        float s = p[a];
#pragma unroll
        for (int o = 16; o > 0; o >>= 1) s += __shfl_down_sync(0xffffffffu, s, o);
        if (lane == 0) out[(size_t)bt * 8 + a] = s + bias[a];
    }
}

__global__ void zero_kernel(float* p, int n) {
    int i = blockIdx.x * 256 + threadIdx.x;
    if (i < n) p[i] = 0.f;
}

/* ---------------- launcher ----------------------------------------------- */
extern "C" void kernel_launch(void* const* d_in, const int* in_sizes, int n_in,
                              void* d_out, int out_size)
{
    const float* feature = (const float*)d_in[0];
    const float* W_embed = (const float*)d_in[1];
    const float* b_embed = (const float*)d_in[2];
    const float* W_ih    = (const float*)d_in[3];
    const float* W_hh    = (const float*)d_in[4];
    const float* b_ih    = (const float*)d_in[5];
    const float* b_hh    = (const float*)d_in[6];
    const float* W_act   = (const float*)d_in[7];
    const float* b_act   = (const float*)d_in[8];
    const float* W_activ = (const float*)d_in[9];
    const float* b_activ = (const float*)d_in[10];
    float* out = (float*)d_out;

    float *px, *pgx, *phid, *ph0, *ph1;
    cudaGetSymbolAddress((void**)&px,   g_x);
    cudaGetSymbolAddress((void**)&pgx,  g_gx);
    cudaGetSymbolAddress((void**)&phid, g_hid);
    cudaGetSymbolAddress((void**)&ph0,  g_h0);
    cudaGetSymbolAddress((void**)&ph1,  g_h1);

    /* h0 = 0 */
    zero_kernel<<<(CBP*CH + 255)/256, 256>>>(ph0, CBP*CH);

    /* x = tanh(feature @ W_embed^T + b_embed)  [15360,1024] */
    gemm_f32x2<<<dim3(CH/BN, CM/BM), 256>>>(feature, W_embed, b_embed, px,
                                            CH, CE, 1);
    /* gx = x @ W_ih^T + b_ih                   [15360,3072] */
    gemm_f32x2<<<dim3(3*CH/BN, CM/BM), 256>>>(px, W_ih, b_ih, pgx,
                                              3*CH, CH, 0);

    /* GRU scan, double-buffered state */
    float* hin = ph0;
    float* hout = ph1;
    for (int t = 0; t < CT; ++t) {
        gru_step<<<dim3(CH/GBJ, CBP/GBM), 128>>>(hin, hout, pgx, W_hh, b_hh,
                                                 phid, t);
        float* tmp = hin; hin = hout; hout = tmp;
    }

    /* heads: action logits [15360,9] then activity logits [1280,8] */
    action_head<<<CM/8, 256>>>(phid, W_act, b_act, out);
    activity_head<<<(CB*CT)/8, 256>>>(phid, W_activ, b_activ,
                                      out + (size_t)CM * 9);
}